// round 5
// baseline (speedup 1.0000x reference)
#include <cuda_runtime.h>
#include <cuda_fp16.h>
#include <cstdint>

// Problem constants
#define VOCAB 131072
#define EMB   128
#define HID   256
#define OUT_N 128
#define BATCH 256
#define SEQ_T 512

// Scratch (device globals; no allocations allowed)
__device__ __half g_pre[(size_t)SEQ_T * BATCH * HID];  // [T][B][HID] fp16, includes b_ih+b_hh
__device__ float  g_hT[BATCH * HID];                   // final hidden state fp32
__device__ int    g_x_is64;                            // 1 if x buffer is int64, else 0

// ---------------------------------------------------------------------------
// mma.sync m16n8k16 row.col f32.f16.f16.f32
// ---------------------------------------------------------------------------
__device__ __forceinline__ void mma16816(float c[4],
                                         unsigned a0, unsigned a1, unsigned a2, unsigned a3,
                                         unsigned b0, unsigned b1) {
    asm volatile(
        "mma.sync.aligned.m16n8k16.row.col.f32.f16.f16.f32 "
        "{%0,%1,%2,%3}, {%4,%5,%6,%7}, {%8,%9}, {%0,%1,%2,%3};\n"
        : "+f"(c[0]), "+f"(c[1]), "+f"(c[2]), "+f"(c[3])
        : "r"(a0), "r"(a1), "r"(a2), "r"(a3), "r"(b0), "r"(b1));
}

// ldmatrix x4: A fragments for m16k16 from shared memory
__device__ __forceinline__ void ldsm4(unsigned& a0, unsigned& a1, unsigned& a2, unsigned& a3,
                                      unsigned addr) {
    asm volatile("ldmatrix.sync.aligned.m8n8.x4.shared.b16 {%0,%1,%2,%3}, [%4];"
                 : "=r"(a0), "=r"(a1), "=r"(a2), "=r"(a3)
                 : "r"(addr));
}

// tanh with ONE MUFU (EX2). rcp done on FMA pipe: bit-hack + 2 Newton (~6e-6 rel).
__device__ __forceinline__ float tanh_fast(float x) {
    float xx = fminf(fmaxf(x, -15.0f), 15.0f);
    float e = __expf(xx + xx);            // MUFU EX2 (+1 mul)
    float d = e + 1.0f;                   // d in [1, ~3e13]
    float r = __uint_as_float(0x7EF311C3u - __float_as_uint(d));
    r = r * (2.0f - d * r);
    r = r * (2.0f - d * r);
    return fmaf(-2.0f, r, 1.0f);          // 1 - 2/(e^{2x}+1)
}

__device__ __forceinline__ unsigned pack_half2(float a, float b) {
    __half2 h = __floats2half2_rn(a, b);
    return *reinterpret_cast<unsigned*>(&h);
}

// ---------------------------------------------------------------------------
// Kernel 0: detect x dtype reading ONLY the first 131072 words (in-bounds for
// both int32 and int64 layouts). int64-LE => odd words (high halves) all zero.
// ---------------------------------------------------------------------------
__global__ void k_detect_x64(const unsigned* __restrict__ xw) {
    __shared__ int s_any;
    if (threadIdx.x == 0) s_any = 0;
    __syncthreads();
    unsigned acc = 0;
    for (int i = threadIdx.x; i < (BATCH * SEQ_T) / 2; i += 256)
        acc |= xw[2 * i + 1];
    if (acc) atomicOr(&s_any, 1);
    __syncthreads();
    if (threadIdx.x == 0) g_x_is64 = (s_any == 0) ? 1 : 0;
}

__device__ __forceinline__ int load_index(const unsigned* xw, int pos) {
    return (int)(g_x_is64 ? xw[2 * pos] : xw[pos]);
}

// ---------------------------------------------------------------------------
// Kernel 1: pre[t][b][:] = emb[x[b,t]] @ W_ih^T + (b_ih + b_hh), stored fp16.
// grid: 256 blocks x 4 tiles of 128 tokens; block 256 threads (2M x 4N warps)
// ---------------------------------------------------------------------------
#define K1_ASTRIDE 136   // halves per row (128 + 8 pad)
#define K1_SMEM_BYTES ((128 * K1_ASTRIDE + 256 * K1_ASTRIDE) * 2 + 256 * 4)

__global__ __launch_bounds__(256, 1) void k_pre(const unsigned* __restrict__ xw,
                                                const float* __restrict__ emb,
                                                const float* __restrict__ W_ih,
                                                const float* __restrict__ b_ih,
                                                const float* __restrict__ b_hh) {
    extern __shared__ char smem[];
    __half (*Asm)[K1_ASTRIDE] = reinterpret_cast<__half(*)[K1_ASTRIDE]>(smem);
    __half (*Bsm)[K1_ASTRIDE] = reinterpret_cast<__half(*)[K1_ASTRIDE]>(smem + 128 * K1_ASTRIDE * 2);
    float* bias = reinterpret_cast<float*>(smem + (128 + 256) * K1_ASTRIDE * 2);

    const int tid  = threadIdx.x;
    const int wid  = tid >> 5;
    const int lane = tid & 31;
    const int r    = lane >> 2;
    const int cq   = lane & 3;
    const int wm   = wid & 1;
    const int wn   = wid >> 1;

    bias[tid] = b_ih[tid] + b_hh[tid];

    for (int i = tid; i < 256 * 128 / 4; i += 256) {
        int n  = i >> 5;
        int k4 = i & 31;
        float4 v = reinterpret_cast<const float4*>(W_ih)[i];
        __half2* dst = reinterpret_cast<__half2*>(&Bsm[n][k4 * 4]);
        dst[0] = __floats2half2_rn(v.x, v.y);
        dst[1] = __floats2half2_rn(v.z, v.w);
    }

    for (int it = 0; it < 4; it++) {
        const int i0 = (blockIdx.x * 4 + it) * 128;
        __syncthreads();

        {
            int tok = tid >> 1, hf = tid & 1;
            int gi = i0 + tok;
            int t = gi >> 8;
            int b = gi & 255;
            int idx = load_index(xw, b * SEQ_T + t);
            const float4* src = reinterpret_cast<const float4*>(emb + (size_t)idx * EMB + hf * 64);
            __half2* dst = reinterpret_cast<__half2*>(&Asm[tok][hf * 64]);
#pragma unroll
            for (int q = 0; q < 16; q++) {
                float4 v = src[q];
                dst[q * 2 + 0] = __floats2half2_rn(v.x, v.y);
                dst[q * 2 + 1] = __floats2half2_rn(v.z, v.w);
            }
        }
        __syncthreads();

        float c[4][8][4];
#pragma unroll
        for (int mt = 0; mt < 4; mt++)
#pragma unroll
            for (int nt = 0; nt < 8; nt++)
#pragma unroll
                for (int q = 0; q < 4; q++) c[mt][nt][q] = 0.0f;

#pragma unroll
        for (int kt = 0; kt < 8; kt++) {
            unsigned a[4][4];
#pragma unroll
            for (int mt = 0; mt < 4; mt++) {
                int row = wm * 64 + mt * 16;
                int k0 = kt * 16 + 2 * cq;
                a[mt][0] = *reinterpret_cast<const unsigned*>(&Asm[row + r][k0]);
                a[mt][1] = *reinterpret_cast<const unsigned*>(&Asm[row + r + 8][k0]);
                a[mt][2] = *reinterpret_cast<const unsigned*>(&Asm[row + r][k0 + 8]);
                a[mt][3] = *reinterpret_cast<const unsigned*>(&Asm[row + r + 8][k0 + 8]);
            }
#pragma unroll
            for (int nt = 0; nt < 8; nt++) {
                int n = wn * 64 + nt * 8 + r;
                int k0 = kt * 16 + 2 * cq;
                unsigned b0 = *reinterpret_cast<const unsigned*>(&Bsm[n][k0]);
                unsigned b1 = *reinterpret_cast<const unsigned*>(&Bsm[n][k0 + 8]);
#pragma unroll
                for (int mt = 0; mt < 4; mt++) mma16816(c[mt][nt], a[mt][0], a[mt][1], a[mt][2], a[mt][3], b0, b1);
            }
        }

        // epilogue: add bias, store fp16
#pragma unroll
        for (int mt = 0; mt < 4; mt++) {
#pragma unroll
            for (int nt = 0; nt < 8; nt++) {
                int row = i0 + wm * 64 + mt * 16 + r;
                int col = wn * 64 + nt * 8 + 2 * cq;
                float bx = bias[col], by = bias[col + 1];
                *reinterpret_cast<__half2*>(&g_pre[(size_t)row * HID + col]) =
                    __floats2half2_rn(c[mt][nt][0] + bx, c[mt][nt][1] + by);
                *reinterpret_cast<__half2*>(&g_pre[(size_t)(row + 8) * HID + col]) =
                    __floats2half2_rn(c[mt][nt][2] + bx, c[mt][nt][3] + by);
            }
        }
    }
}

// ---------------------------------------------------------------------------
// Kernel 2: RNN recurrence. 16 CTAs x 16 batch rows. W_hh fragments in regs,
// h double-buffered fp16 in smem, A via ldmatrix.x4, two nt-phases so the
// phase-1 tanh epilogue overlaps phase-2 mma.
// ---------------------------------------------------------------------------
#define K2_WSTRIDE 264  // 256 + 8 pad halves
#define K2_SMEM_BYTES ((256 * K2_WSTRIDE + 32 * K2_WSTRIDE) * 2)

__global__ __launch_bounds__(256, 1) void k_rnn(const float* __restrict__ W_hh) {
    extern __shared__ char smem[];
    __half (*Wsm)[K2_WSTRIDE] = reinterpret_cast<__half(*)[K2_WSTRIDE]>(smem);
    __half (*Hbuf)[K2_WSTRIDE] = reinterpret_cast<__half(*)[K2_WSTRIDE]>(smem + 256 * K2_WSTRIDE * 2);

    const int tid  = threadIdx.x;
    const int wid  = tid >> 5;
    const int lane = tid & 31;
    const int r    = lane >> 2;
    const int cq   = lane & 3;
    const int wn   = wid * 32;
    const int bRow0 = blockIdx.x * 16;

    // W_hh fp32 -> Wsm fp16 [n][k]
    for (int i = tid; i < 256 * 256 / 4; i += 256) {
        int n  = i >> 6;
        int k4 = i & 63;
        float4 v = reinterpret_cast<const float4*>(W_hh)[i];
        __half2* dst = reinterpret_cast<__half2*>(&Wsm[n][k4 * 4]);
        dst[0] = __floats2half2_rn(v.x, v.y);
        dst[1] = __floats2half2_rn(v.z, v.w);
    }
    for (int i = tid; i < 32 * K2_WSTRIDE; i += 256)
        reinterpret_cast<__half*>(Hbuf)[i] = __ushort_as_half(0);
    __syncthreads();

    // register-resident B fragments
    unsigned bfr[16][4][2];
#pragma unroll
    for (int kt = 0; kt < 16; kt++)
#pragma unroll
        for (int nt = 0; nt < 4; nt++) {
            int n = wn + nt * 8 + r;
            int k0 = kt * 16 + 2 * cq;
            bfr[kt][nt][0] = *reinterpret_cast<const unsigned*>(&Wsm[n][k0]);
            bfr[kt][nt][1] = *reinterpret_cast<const unsigned*>(&Wsm[n][k0 + 8]);
        }

    // ldmatrix per-lane address offset (halves): lanes 0-15 -> rows 0-15 @k0,
    // lanes 16-31 -> rows 0-15 @k0+8
    const unsigned hbase = (unsigned)__cvta_generic_to_shared(&Hbuf[0][0]);
    const unsigned laneoff = (unsigned)((lane & 15) * K2_WSTRIDE + (lane >> 4) * 8);

    int cur = 0;
    for (int t = 0; t < SEQ_T; t++) {
        // prefetch pre (fp16)
        const __half* pt = g_pre + ((size_t)t * BATCH + bRow0) * HID;
        __half2 ph[4][2];
#pragma unroll
        for (int nt = 0; nt < 4; nt++) {
            int col = wn + nt * 8 + 2 * cq;
            ph[nt][0] = *reinterpret_cast<const __half2*>(pt + (size_t)r * HID + col);
            ph[nt][1] = *reinterpret_cast<const __half2*>(pt + (size_t)(r + 8) * HID + col);
        }

        float acc[4][4];
#pragma unroll
        for (int nt = 0; nt < 4; nt++)
#pragma unroll
            for (int q = 0; q < 4; q++) acc[nt][q] = 0.0f;

        const unsigned hb = hbase + (unsigned)(cur * 16 * K2_WSTRIDE + 0) * 2u;

        // phase 1: nt 0,1
#pragma unroll
        for (int kt = 0; kt < 16; kt++) {
            unsigned a0, a1, a2, a3;
            ldsm4(a0, a1, a2, a3, hb + (laneoff + kt * 16) * 2u);
            mma16816(acc[0], a0, a1, a2, a3, bfr[kt][0][0], bfr[kt][0][1]);
            mma16816(acc[1], a0, a1, a2, a3, bfr[kt][1][0], bfr[kt][1][1]);
        }
        // phase 2: nt 2,3 (independent of phase-1 epilogue -> overlap)
#pragma unroll
        for (int kt = 0; kt < 16; kt++) {
            unsigned a0, a1, a2, a3;
            ldsm4(a0, a1, a2, a3, hb + (laneoff + kt * 16) * 2u);
            mma16816(acc[2], a0, a1, a2, a3, bfr[kt][2][0], bfr[kt][2][1]);
            mma16816(acc[3], a0, a1, a2, a3, bfr[kt][3][0], bfr[kt][3][1]);
        }

        // epilogue: h_new = tanh(acc + pre)
        __half (*hn)[K2_WSTRIDE] = Hbuf + (cur ^ 1) * 16;
#pragma unroll
        for (int nt = 0; nt < 4; nt++) {
            int col = wn + nt * 8 + 2 * cq;
            float2 p0 = __half22float2(ph[nt][0]);
            float2 p1 = __half22float2(ph[nt][1]);
            float y0 = tanh_fast(acc[nt][0] + p0.x);
            float y1 = tanh_fast(acc[nt][1] + p0.y);
            float y2 = tanh_fast(acc[nt][2] + p1.x);
            float y3 = tanh_fast(acc[nt][3] + p1.y);
            *reinterpret_cast<unsigned*>(&hn[r][col]) = pack_half2(y0, y1);
            *reinterpret_cast<unsigned*>(&hn[r + 8][col]) = pack_half2(y2, y3);
            if (t == SEQ_T - 1) {
                *reinterpret_cast<float2*>(&g_hT[(size_t)(bRow0 + r) * HID + col]) = make_float2(y0, y1);
                *reinterpret_cast<float2*>(&g_hT[(size_t)(bRow0 + r + 8) * HID + col]) = make_float2(y2, y3);
            }
        }
        cur ^= 1;
        __syncthreads();
    }
}

// ---------------------------------------------------------------------------
// Kernel 3: y = hT @ Wp^T + bp, layernorm over OUT=128.
// grid 32 (8 batch rows each), 128 threads (one per output col).
// Wp transposed into smem fp16 (stride 130, conflict-free), h rows in smem.
// ---------------------------------------------------------------------------
#define WT_STRIDE 130
#define KH_SMEM_BYTES (HID * WT_STRIDE * 2 + 8 * HID * 4)

__global__ __launch_bounds__(128) void k_head(const float* __restrict__ Wp,
                                              const float* __restrict__ bp,
                                              const float* __restrict__ gamma,
                                              const float* __restrict__ beta,
                                              float* __restrict__ out) {
    extern __shared__ char sm[];
    __half* wT = reinterpret_cast<__half*>(sm);                 // [k][WT_STRIDE]
    float*  h8 = reinterpret_cast<float*>(sm + HID * WT_STRIDE * 2);  // [8][HID]
    __shared__ float red[2][4];

    const int tid = threadIdx.x;
    const int lane = tid & 31, wrp = tid >> 5;
    const int b0 = blockIdx.x * 8;

    for (int idx = tid; idx < OUT_N * HID; idx += 128) {
        int o = idx >> 8;          // HID = 256
        int k = idx & (HID - 1);
        wT[k * WT_STRIDE + o] = __float2half_rn(Wp[idx]);
    }
    for (int idx = tid; idx < 8 * HID; idx += 128)
        h8[idx] = g_hT[(size_t)b0 * HID + idx];
    __syncthreads();

    const int o = tid;
    float acc[8];
#pragma unroll
    for (int j = 0; j < 8; j++) acc[j] = 0.0f;

    for (int k = 0; k < HID; k += 4) {
        float w0 = __half2float(wT[(k + 0) * WT_STRIDE + o]);
        float w1 = __half2float(wT[(k + 1) * WT_STRIDE + o]);
        float w2 = __half2float(wT[(k + 2) * WT_STRIDE + o]);
        float w3 = __half2float(wT[(k + 3) * WT_STRIDE + o]);
#pragma unroll
        for (int j = 0; j < 8; j++) {
            float4 hv = *reinterpret_cast<const float4*>(&h8[j * HID + k]);
            acc[j] = fmaf(hv.x, w0, acc[j]);
            acc[j] = fmaf(hv.y, w1, acc[j]);
            acc[j] = fmaf(hv.z, w2, acc[j]);
            acc[j] = fmaf(hv.w, w3, acc[j]);
        }
    }

    const float bpo = bp[o], gm = gamma[o], bt = beta[o];
#pragma unroll 1
    for (int j = 0; j < 8; j++) {
        float y = acc[j] + bpo;
        float s1 = y, s2 = y * y;
#pragma unroll
        for (int off = 16; off > 0; off >>= 1) {
            s1 += __shfl_down_sync(0xffffffffu, s1, off);
            s2 += __shfl_down_sync(0xffffffffu, s2, off);
        }
        if (lane == 0) { red[0][wrp] = s1; red[1][wrp] = s2; }
        __syncthreads();
        float S1 = red[0][0] + red[0][1] + red[0][2] + red[0][3];
        float S2 = red[1][0] + red[1][1] + red[1][2] + red[1][3];
        float mu = S1 * (1.0f / OUT_N);
        float var = S2 * (1.0f / OUT_N) - mu * mu;
        float inv = rsqrtf(var + 1e-5f);
        out[(size_t)(b0 + j) * OUT_N + o] = (y - mu) * inv * gm + bt;
        __syncthreads();
    }
}

// ---------------------------------------------------------------------------
extern "C" void kernel_launch(void* const* d_in, const int* in_sizes, int n_in,
                              void* d_out, int out_size) {
    const unsigned* xw = (const unsigned*)d_in[0];
    const float* emb   = (const float*)d_in[1];
    const float* W_ih  = (const float*)d_in[2];
    const float* W_hh  = (const float*)d_in[3];
    const float* b_ih  = (const float*)d_in[4];
    const float* b_hh  = (const float*)d_in[5];
    const float* Wp    = (const float*)d_in[6];
    const float* bp    = (const float*)d_in[7];
    const float* gamma = (const float*)d_in[8];
    const float* beta  = (const float*)d_in[9];
    float* out = (float*)d_out;

    cudaFuncSetAttribute(k_pre,  cudaFuncAttributeMaxDynamicSharedMemorySize, K1_SMEM_BYTES);
    cudaFuncSetAttribute(k_rnn,  cudaFuncAttributeMaxDynamicSharedMemorySize, K2_SMEM_BYTES);
    cudaFuncSetAttribute(k_head, cudaFuncAttributeMaxDynamicSharedMemorySize, KH_SMEM_BYTES);

    k_detect_x64<<<1, 256>>>(xw);
    k_pre<<<256, 256, K1_SMEM_BYTES>>>(xw, emb, W_ih, b_ih, b_hh);
    k_rnn<<<16, 256, K2_SMEM_BYTES>>>(W_hh);
    k_head<<<32, 128, KH_SMEM_BYTES>>>(Wp, bp, gamma, beta, out);
}

// round 6
// speedup vs baseline: 1.8417x; 1.8417x over previous
#include <cuda_runtime.h>
#include <cuda_fp16.h>
#include <cstdint>

// Problem constants
#define VOCAB 131072
#define EMB   128
#define HID   256
#define OUT_N 128
#define BATCH 256
#define SEQ_T 512

// Scratch (device globals; no allocations allowed)
__device__ __half g_pre[(size_t)SEQ_T * BATCH * HID];  // [T][B][HID] fp16, includes b_ih+b_hh
__device__ float  g_hT[BATCH * HID];                   // final hidden state fp32
__device__ int    g_x_is64;                            // 1 if x buffer is int64, else 0

// ---------------------------------------------------------------------------
// mma.sync m16n8k16 row.col f32.f16.f16.f32
// ---------------------------------------------------------------------------
__device__ __forceinline__ void mma16816(float c[4],
                                         unsigned a0, unsigned a1, unsigned a2, unsigned a3,
                                         unsigned b0, unsigned b1) {
    asm volatile(
        "mma.sync.aligned.m16n8k16.row.col.f32.f16.f16.f32 "
        "{%0,%1,%2,%3}, {%4,%5,%6,%7}, {%8,%9}, {%0,%1,%2,%3};\n"
        : "+f"(c[0]), "+f"(c[1]), "+f"(c[2]), "+f"(c[3])
        : "r"(a0), "r"(a1), "r"(a2), "r"(a3), "r"(b0), "r"(b1));
}

// ldmatrix x2: B fragments (8 rows x 16 cols b16) from shared memory
__device__ __forceinline__ void ldsm2(unsigned& b0, unsigned& b1, unsigned addr) {
    asm volatile("ldmatrix.sync.aligned.m8n8.x2.shared.b16 {%0,%1}, [%2];"
                 : "=r"(b0), "=r"(b1)
                 : "r"(addr));
}

// hardware tanh approximation (sm_75+), single MUFU op
__device__ __forceinline__ float tanh_approx(float x) {
    float y;
    asm("tanh.approx.f32 %0, %1;" : "=f"(y) : "f"(x));
    return y;
}

// accurate tanh (used on the final step): 1 - 2/(e^{2x}+1), ~1e-6 rel
__device__ __forceinline__ float tanh_fast(float x) {
    float xx = fminf(fmaxf(x, -15.0f), 15.0f);
    float e = __expf(xx + xx);
    float d = e + 1.0f;
    float r = __uint_as_float(0x7EF311C3u - __float_as_uint(d));
    r = r * (2.0f - d * r);
    r = r * (2.0f - d * r);
    return fmaf(-2.0f, r, 1.0f);
}

// ---------------------------------------------------------------------------
// Kernel 0: detect x dtype reading ONLY the first 131072 words (in-bounds for
// both int32 and int64 layouts). int64-LE => odd words (high halves) all zero.
// ---------------------------------------------------------------------------
__global__ void k_detect_x64(const unsigned* __restrict__ xw) {
    __shared__ int s_any;
    if (threadIdx.x == 0) s_any = 0;
    __syncthreads();
    unsigned acc = 0;
    for (int i = threadIdx.x; i < (BATCH * SEQ_T) / 2; i += 256)
        acc |= xw[2 * i + 1];
    if (acc) atomicOr(&s_any, 1);
    __syncthreads();
    if (threadIdx.x == 0) g_x_is64 = (s_any == 0) ? 1 : 0;
}

__device__ __forceinline__ int load_index(const unsigned* xw, int pos) {
    return (int)(g_x_is64 ? xw[2 * pos] : xw[pos]);
}

// ---------------------------------------------------------------------------
// Kernel 1: pre[t][b][:] = emb[x[b,t]] @ W_ih^T + (b_ih + b_hh), stored fp16.
// grid: 256 blocks x 4 tiles of 128 tokens; block 256 threads (2M x 4N warps)
// ---------------------------------------------------------------------------
#define K1_ASTRIDE 136   // halves per row (128 + 8 pad)
#define K1_SMEM_BYTES ((128 * K1_ASTRIDE + 256 * K1_ASTRIDE) * 2 + 256 * 4)

__global__ __launch_bounds__(256, 1) void k_pre(const unsigned* __restrict__ xw,
                                                const float* __restrict__ emb,
                                                const float* __restrict__ W_ih,
                                                const float* __restrict__ b_ih,
                                                const float* __restrict__ b_hh) {
    extern __shared__ char smem[];
    __half (*Asm)[K1_ASTRIDE] = reinterpret_cast<__half(*)[K1_ASTRIDE]>(smem);
    __half (*Bsm)[K1_ASTRIDE] = reinterpret_cast<__half(*)[K1_ASTRIDE]>(smem + 128 * K1_ASTRIDE * 2);
    float* bias = reinterpret_cast<float*>(smem + (128 + 256) * K1_ASTRIDE * 2);

    const int tid  = threadIdx.x;
    const int wid  = tid >> 5;
    const int lane = tid & 31;
    const int r    = lane >> 2;
    const int cq   = lane & 3;
    const int wm   = wid & 1;
    const int wn   = wid >> 1;

    bias[tid] = b_ih[tid] + b_hh[tid];

    for (int i = tid; i < 256 * 128 / 4; i += 256) {
        int n  = i >> 5;
        int k4 = i & 31;
        float4 v = reinterpret_cast<const float4*>(W_ih)[i];
        __half2* dst = reinterpret_cast<__half2*>(&Bsm[n][k4 * 4]);
        dst[0] = __floats2half2_rn(v.x, v.y);
        dst[1] = __floats2half2_rn(v.z, v.w);
    }

    for (int it = 0; it < 4; it++) {
        const int i0 = (blockIdx.x * 4 + it) * 128;
        __syncthreads();

        {
            int tok = tid >> 1, hf = tid & 1;
            int gi = i0 + tok;
            int t = gi >> 8;
            int b = gi & 255;
            int idx = load_index(xw, b * SEQ_T + t);
            const float4* src = reinterpret_cast<const float4*>(emb + (size_t)idx * EMB + hf * 64);
            __half2* dst = reinterpret_cast<__half2*>(&Asm[tok][hf * 64]);
#pragma unroll
            for (int q = 0; q < 16; q++) {
                float4 v = src[q];
                dst[q * 2 + 0] = __floats2half2_rn(v.x, v.y);
                dst[q * 2 + 1] = __floats2half2_rn(v.z, v.w);
            }
        }
        __syncthreads();

        float c[4][8][4];
#pragma unroll
        for (int mt = 0; mt < 4; mt++)
#pragma unroll
            for (int nt = 0; nt < 8; nt++)
#pragma unroll
                for (int q = 0; q < 4; q++) c[mt][nt][q] = 0.0f;

#pragma unroll
        for (int kt = 0; kt < 8; kt++) {
            unsigned a[4][4];
#pragma unroll
            for (int mt = 0; mt < 4; mt++) {
                int row = wm * 64 + mt * 16;
                int k0 = kt * 16 + 2 * cq;
                a[mt][0] = *reinterpret_cast<const unsigned*>(&Asm[row + r][k0]);
                a[mt][1] = *reinterpret_cast<const unsigned*>(&Asm[row + r + 8][k0]);
                a[mt][2] = *reinterpret_cast<const unsigned*>(&Asm[row + r][k0 + 8]);
                a[mt][3] = *reinterpret_cast<const unsigned*>(&Asm[row + r + 8][k0 + 8]);
            }
#pragma unroll
            for (int nt = 0; nt < 8; nt++) {
                int n = wn * 64 + nt * 8 + r;
                int k0 = kt * 16 + 2 * cq;
                unsigned b0 = *reinterpret_cast<const unsigned*>(&Bsm[n][k0]);
                unsigned b1 = *reinterpret_cast<const unsigned*>(&Bsm[n][k0 + 8]);
#pragma unroll
                for (int mt = 0; mt < 4; mt++) mma16816(c[mt][nt], a[mt][0], a[mt][1], a[mt][2], a[mt][3], b0, b1);
            }
        }

        // epilogue: add bias, store fp16
#pragma unroll
        for (int mt = 0; mt < 4; mt++) {
#pragma unroll
            for (int nt = 0; nt < 8; nt++) {
                int row = i0 + wm * 64 + mt * 16 + r;
                int col = wn * 64 + nt * 8 + 2 * cq;
                float bx = bias[col], by = bias[col + 1];
                *reinterpret_cast<__half2*>(&g_pre[(size_t)row * HID + col]) =
                    __floats2half2_rn(c[mt][nt][0] + bx, c[mt][nt][1] + by);
                *reinterpret_cast<__half2*>(&g_pre[(size_t)(row + 8) * HID + col]) =
                    __floats2half2_rn(c[mt][nt][2] + bx, c[mt][nt][3] + by);
            }
        }
    }
}

// ---------------------------------------------------------------------------
// Kernel 2: RNN recurrence, operand-swapped: W_hh is the A operand (M=256
// hid-out), h is the B operand (N=8 batch rows). 32 CTAs x 8 batch rows.
// Per warp per step: 32 mma + 16 ldsm.x2, A fragments register-resident.
// tanh.approx (1 MUFU) for steps 0..T-2, accurate tanh on the final step.
// ---------------------------------------------------------------------------
#define K2_WSTRIDE 264  // 256 + 8 pad halves
#define K2_SMEM_BYTES ((256 * K2_WSTRIDE + 2 * 8 * K2_WSTRIDE) * 2)

__global__ __launch_bounds__(256, 1) void k_rnn(const float* __restrict__ W_hh) {
    extern __shared__ char smem[];
    __half (*Wsm)[K2_WSTRIDE] = reinterpret_cast<__half(*)[K2_WSTRIDE]>(smem);      // [m=hid_out][k]
    __half* Hbuf = reinterpret_cast<__half*>(smem + 256 * K2_WSTRIDE * 2);          // [2][8][K2_WSTRIDE]

    const int tid  = threadIdx.x;
    const int wid  = tid >> 5;
    const int lane = tid & 31;
    const int r    = lane >> 2;
    const int cq   = lane & 3;
    const int ms   = wid * 32;           // warp's hid-out slice (2 m-tiles)
    const int b0   = blockIdx.x * 8;     // this CTA's 8 batch rows

    // W_hh [m][k] fp32 -> Wsm fp16
    for (int i = tid; i < 256 * 256 / 4; i += 256) {
        int m  = i >> 6;
        int k4 = i & 63;
        float4 v = reinterpret_cast<const float4*>(W_hh)[i];
        __half2* dst = reinterpret_cast<__half2*>(&Wsm[m][k4 * 4]);
        dst[0] = __floats2half2_rn(v.x, v.y);
        dst[1] = __floats2half2_rn(v.z, v.w);
    }
    // zero both h buffers (h0 = 0)
    for (int i = tid; i < 2 * 8 * K2_WSTRIDE; i += 256)
        Hbuf[i] = __ushort_as_half(0);
    __syncthreads();

    // register-resident A fragments: 16 k-tiles x 2 m-tiles x 4 regs = 128 regs
    unsigned afr[16][2][4];
#pragma unroll
    for (int kt = 0; kt < 16; kt++)
#pragma unroll
        for (int mt = 0; mt < 2; mt++) {
            int m  = ms + mt * 16;
            int kq = kt * 16 + 2 * cq;
            afr[kt][mt][0] = *reinterpret_cast<const unsigned*>(&Wsm[m + r][kq]);
            afr[kt][mt][1] = *reinterpret_cast<const unsigned*>(&Wsm[m + r + 8][kq]);
            afr[kt][mt][2] = *reinterpret_cast<const unsigned*>(&Wsm[m + r][kq + 8]);
            afr[kt][mt][3] = *reinterpret_cast<const unsigned*>(&Wsm[m + r + 8][kq + 8]);
        }

    // ldmatrix.x2 lane address: lanes 0-7 -> rows 0-7 @k0; lanes 8-15 -> rows 0-7 @k0+8
    const unsigned hbase = (unsigned)__cvta_generic_to_shared(Hbuf);
    const unsigned laneoffB = (unsigned)((lane & 7) * K2_WSTRIDE + ((lane >> 3) & 1) * 8);

    int cur = 0;
    for (int t = 0; t < SEQ_T; t++) {
        // prefetch this step's pre values (8 scalars, hidden under mma)
        const __half* pt = g_pre + ((size_t)t * BATCH + b0) * HID;
        __half ph[2][4];
#pragma unroll
        for (int mt = 0; mt < 2; mt++) {
            int m = ms + mt * 16;
            ph[mt][0] = pt[(size_t)(2 * cq + 0) * HID + m + r];
            ph[mt][1] = pt[(size_t)(2 * cq + 1) * HID + m + r];
            ph[mt][2] = pt[(size_t)(2 * cq + 0) * HID + m + r + 8];
            ph[mt][3] = pt[(size_t)(2 * cq + 1) * HID + m + r + 8];
        }

        float c[2][4];
#pragma unroll
        for (int mt = 0; mt < 2; mt++)
#pragma unroll
            for (int q = 0; q < 4; q++) c[mt][q] = 0.0f;

        const unsigned hb = hbase + (unsigned)(cur * 8 * K2_WSTRIDE) * 2u + laneoffB * 2u;
#pragma unroll
        for (int kt = 0; kt < 16; kt++) {
            unsigned bf0, bf1;
            ldsm2(bf0, bf1, hb + kt * 32u);   // 16 halves = 32 bytes per k-tile
            mma16816(c[0], afr[kt][0][0], afr[kt][0][1], afr[kt][0][2], afr[kt][0][3], bf0, bf1);
            mma16816(c[1], afr[kt][1][0], afr[kt][1][1], afr[kt][1][2], afr[kt][1][3], bf0, bf1);
        }

        // epilogue: h_new[b][m] = tanh(c + pre); write into the other buffer.
        // thread value q: q0 -> (m+r,   b=2cq), q1 -> (m+r,   b=2cq+1)
        //                 q2 -> (m+r+8, b=2cq), q3 -> (m+r+8, b=2cq+1)
        __half* hn = Hbuf + (cur ^ 1) * 8 * K2_WSTRIDE;
        const bool last = (t == SEQ_T - 1);
#pragma unroll
        for (int mt = 0; mt < 2; mt++) {
            int m = ms + mt * 16;
#pragma unroll
            for (int q = 0; q < 4; q++) {
                int hid = m + r + (q >> 1) * 8;
                int b   = 2 * cq + (q & 1);
                float v = c[mt][q] + __half2float(ph[mt][q]);
                float y = last ? tanh_fast(v) : tanh_approx(v);
                hn[b * K2_WSTRIDE + hid] = __float2half_rn(y);
                if (last) g_hT[(size_t)(b0 + b) * HID + hid] = y;
            }
        }
        cur ^= 1;
        __syncthreads();
    }
}

// ---------------------------------------------------------------------------
// Kernel 3: y = hT @ Wp^T + bp, layernorm over OUT=128.  (R3 version, 17us)
// grid 256 (one block per batch row), 128 threads (one per output)
// ---------------------------------------------------------------------------
__global__ __launch_bounds__(128) void k_head(const float* __restrict__ Wp,
                                              const float* __restrict__ bp,
                                              const float* __restrict__ gamma,
                                              const float* __restrict__ beta,
                                              float* __restrict__ out) {
    const int b = blockIdx.x;
    const int o = threadIdx.x;
    const int lane = o & 31, wid = o >> 5;

    const float* h = g_hT + (size_t)b * HID;
    const float* w = Wp + (size_t)o * HID;
    float s = 0.0f;
#pragma unroll 8
    for (int k = 0; k < HID; k += 4) {
        float4 hv = *reinterpret_cast<const float4*>(h + k);
        float4 wv = *reinterpret_cast<const float4*>(w + k);
        s += hv.x * wv.x + hv.y * wv.y + hv.z * wv.z + hv.w * wv.w;
    }
    float y = s + bp[o];

    float s1 = y, s2 = y * y;
#pragma unroll
    for (int off = 16; off > 0; off >>= 1) {
        s1 += __shfl_down_sync(0xffffffffu, s1, off);
        s2 += __shfl_down_sync(0xffffffffu, s2, off);
    }
    __shared__ float r1[4], r2[4];
    if (lane == 0) { r1[wid] = s1; r2[wid] = s2; }
    __syncthreads();
    float S1 = r1[0] + r1[1] + r1[2] + r1[3];
    float S2 = r2[0] + r2[1] + r2[2] + r2[3];
    float mu = S1 * (1.0f / OUT_N);
    float var = S2 * (1.0f / OUT_N) - mu * mu;
    float inv = rsqrtf(var + 1e-5f);
    out[(size_t)b * OUT_N + o] = (y - mu) * inv * gamma[o] + beta[o];
}

// ---------------------------------------------------------------------------
extern "C" void kernel_launch(void* const* d_in, const int* in_sizes, int n_in,
                              void* d_out, int out_size) {
    const unsigned* xw = (const unsigned*)d_in[0];
    const float* emb   = (const float*)d_in[1];
    const float* W_ih  = (const float*)d_in[2];
    const float* W_hh  = (const float*)d_in[3];
    const float* b_ih  = (const float*)d_in[4];
    const float* b_hh  = (const float*)d_in[5];
    const float* Wp    = (const float*)d_in[6];
    const float* bp    = (const float*)d_in[7];
    const float* gamma = (const float*)d_in[8];
    const float* beta  = (const float*)d_in[9];
    float* out = (float*)d_out;

    cudaFuncSetAttribute(k_pre, cudaFuncAttributeMaxDynamicSharedMemorySize, K1_SMEM_BYTES);
    cudaFuncSetAttribute(k_rnn, cudaFuncAttributeMaxDynamicSharedMemorySize, K2_SMEM_BYTES);

    k_detect_x64<<<1, 256>>>(xw);
    k_pre<<<256, 256, K1_SMEM_BYTES>>>(xw, emb, W_ih, b_ih, b_hh);
    k_rnn<<<32, 256, K2_SMEM_BYTES>>>(W_hh);
    k_head<<<256, 128>>>(Wp, bp, gamma, beta, out);
}